// round 5
// baseline (speedup 1.0000x reference)
#include <cuda_runtime.h>
#include <cuda_bf16.h>
#include <cstdint>

#define DIMN 512
#define MT   32
#define NROWS 65536
#define NCTAS (NROWS / MT)        // 2048
#define NTHREADS 256
#define ETA   0.1f
#define OMETA 0.9f

// per-CTA smem: a-tile [32][512] bf16 (32KB) + 2 G chunk buffers [32][512] bf16 (32KB each) + flags
static constexpr uint32_t A_OFF   = 0;
static constexpr uint32_t G_OFF0  = 32768;
static constexpr uint32_t G_OFF1  = 65536;
static constexpr uint32_t FL_OFF  = 98304;        // flags[2][16] uint32 = 128B
static constexpr uint32_t SMEM_TOTAL = 98432;

#define NCH_TOTAL (9 * 16)        // 144 chunks of 32 rows

// G' = -eta * (0.5*(G+G^T)) with zero diagonal, bf16, row-major [K=512][N=512]
__device__ __nv_bfloat16 g_gp[DIMN * DIMN];

__global__ void lca_prep_kernel(const float* __restrict__ G) {
    int idx = blockIdx.x * blockDim.x + threadIdx.x;
    int i = idx >> 9, j = idx & 511;
    float v = (i == j) ? 0.0f : -ETA * 0.5f * (G[idx] + G[j * DIMN + i]);
    g_gp[idx] = __float2bfloat16(v);
}

__device__ __forceinline__ uint32_t smem_u32(const void* p) {
    uint32_t a;
    asm("{ .reg .u64 t; cvta.to.shared.u64 t, %1; cvt.u32.u64 %0, t; }" : "=r"(a) : "l"(p));
    return a;
}
__device__ __forceinline__ void ldsm4(uint32_t* r, uint32_t addr) {
    asm volatile("ldmatrix.sync.aligned.m8n8.x4.shared.b16 {%0,%1,%2,%3}, [%4];"
                 : "=r"(r[0]), "=r"(r[1]), "=r"(r[2]), "=r"(r[3]) : "r"(addr));
}
__device__ __forceinline__ void ldsm4t(uint32_t* r, uint32_t addr) {
    asm volatile("ldmatrix.sync.aligned.m8n8.x4.trans.shared.b16 {%0,%1,%2,%3}, [%4];"
                 : "=r"(r[0]), "=r"(r[1]), "=r"(r[2]), "=r"(r[3]) : "r"(addr));
}
__device__ __forceinline__ void mma_bf16(float* c, const uint32_t* a, uint32_t b0, uint32_t b1) {
    asm volatile("mma.sync.aligned.m16n8k16.row.col.f32.bf16.bf16.f32 "
                 "{%0,%1,%2,%3}, {%4,%5,%6,%7}, {%8,%9}, {%0,%1,%2,%3};"
                 : "+f"(c[0]), "+f"(c[1]), "+f"(c[2]), "+f"(c[3])
                 : "r"(a[0]), "r"(a[1]), "r"(a[2]), "r"(a[3]), "r"(b0), "r"(b1));
}
__device__ __forceinline__ void cp_async16(uint32_t dst, const void* src) {
    asm volatile("cp.async.cg.shared.global [%0], [%1], 16;" :: "r"(dst), "l"(src) : "memory");
}

// load G chunk rb (32 rows, 32KB) into SMEM buffer boff; 2048 16B units, 8 per thread (256 thr)
__device__ __forceinline__ void load_chunk32(uint32_t sb, uint32_t boff, int rb, int tid) {
    const char* src = (const char*)g_gp + (size_t)rb * 32768 + (size_t)tid * 16;
#pragma unroll
    for (int j = 0; j < 8; j++) {
        int q = tid + j * 256;
        int r = q >> 6, cu = q & 63;
        uint32_t dst = sb + boff + (uint32_t)r * 1024u + ((uint32_t)(cu ^ (r & 7)) << 4);
        cp_async16(dst, src + j * 4096);
    }
    asm volatile("cp.async.commit_group;" ::: "memory");
}

__global__ __launch_bounds__(NTHREADS, 2)
void lca_main_kernel(const float* __restrict__ u,
                     const float* __restrict__ log_lam,
                     float* __restrict__ out) {
    extern __shared__ char smem[];
    const uint32_t sb = smem_u32(smem);
    uint32_t* flagsm = reinterpret_cast<uint32_t*>(smem + FL_OFF);   // [2][16]
    const int tid  = threadIdx.x;
    const int lane = tid & 31;
    const int wn   = tid >> 5;             // 0..7 (64-col group); all warps share rows 0..31
    const int n0   = wn * 64;
    const uint32_t un0 = (uint32_t)(n0 >> 3);
    const int grow0 = blockIdx.x * MT;
    const float lam = expf(log_lam[0]);
    const int r4 = lane >> 2;
    const int c2 = (lane & 3) * 2;

    float acc[2][8][4];                     // [m16 half][n8 frag][quad]

    const uint32_t a_lrow0 = sb + A_OFF + (uint32_t)(lane & 15) * 1024u;
    const uint32_t a_lrow1 = a_lrow0 + 16u * 1024u;
    const uint32_t a_cbs = ((uint32_t)(lane >> 4)) ^ ((uint32_t)(lane & 7));
    const uint32_t b_rowoff = (uint32_t)(lane & 15) * 1024u;
    uint32_t b_pu[4];
#pragma unroll
    for (int p = 0; p < 4; p++)
        b_pu[p] = (((un0 + (uint32_t)(2 * p) + (uint32_t)(lane >> 4)) ^ (uint32_t)(lane & 7)) << 4);

    if (tid < 32) flagsm[tid] = 0u;
    load_chunk32(sb, G_OFF0, 0, tid);      // chunk 0 -> buf0 (overlaps init epilogue)

    // ---- init: v1 = eta*u; a1 = soft(v1) -> SMEM + flags slot0; acc = 0.9*v1 + 0.1*u ----
    {
        bool nzlo = false, nzhi = false;
#pragma unroll
        for (int fm = 0; fm < 2; fm++)
#pragma unroll
        for (int rh = 0; rh < 2; rh++) {
            int rl = fm * 16 + rh * 8 + r4;
            const float* urow = u + (size_t)(grow0 + rl) * DIMN;
            uint32_t abase = sb + A_OFF + (uint32_t)rl * 1024u + (uint32_t)(c2 * 2);
            uint32_t sw = (uint32_t)(rl & 7);
#pragma unroll
            for (int ni = 0; ni < 8; ni++) {
                float2 uv = *(const float2*)(urow + n0 + ni * 8 + c2);
                float v0 = ETA * uv.x, v1 = ETA * uv.y;
                float s0 = fabsf(v0) - lam, s1 = fabsf(v1) - lam;
                float a0 = (s0 > 0.0f) ? copysignf(s0, v0) : 0.0f;
                float a1 = (s1 > 0.0f) ? copysignf(s1, v1) : 0.0f;
                bool nz = (a0 != 0.0f) || (a1 != 0.0f);
                if (ni < 4) nzlo |= nz; else nzhi |= nz;
                __nv_bfloat162 h2 = __floats2bfloat162_rn(a0, a1);
                uint32_t aaddr = abase + (((un0 + (uint32_t)ni) ^ sw) << 4);
                asm volatile("st.shared.b32 [%0], %1;" :: "r"(aaddr), "r"(*(uint32_t*)&h2) : "memory");
                acc[fm][ni][rh * 2 + 0] = fmaf(OMETA, v0, ETA * uv.x);
                acc[fm][ni][rh * 2 + 1] = fmaf(OMETA, v1, ETA * uv.y);
            }
        }
        bool wlo = __any_sync(0xFFFFFFFFu, nzlo);
        bool whi = __any_sync(0xFFFFFFFFu, nzhi);
        if (lane == 0) {
            if (wlo) atomicOr(&flagsm[2 * wn + 0], 1u);
            if (whi) atomicOr(&flagsm[2 * wn + 1], 1u);
        }
    }
    asm volatile("cp.async.wait_group 0;" ::: "memory");
    __syncthreads();

    // ---- 9 fused iterations, 16 chunks of 32 G-rows each ----
#pragma unroll 1
    for (int it = 0; it < 9; it++) {
        const int slot = it & 1;
#pragma unroll 1
        for (int kb = 0; kb < 16; kb++) {
            const int c = it * 16 + kb;
            const uint32_t buf = sb + ((c & 1) ? G_OFF1 : G_OFF0);
            if (c + 1 < NCH_TOTAL)
                load_chunk32(sb, ((c & 1) ? G_OFF0 : G_OFF1), (kb + 1) & 15, tid);

            if (flagsm[slot * 16 + kb]) {
                uint32_t Af[2][8], Bf[2][16];
                {   // preload k16 step 0 of this chunk
                    uint32_t aoff = (((uint32_t)(kb << 2) ^ a_cbs) << 4);
                    ldsm4(&Af[0][0], a_lrow0 + aoff);
                    ldsm4(&Af[0][4], a_lrow1 + aoff);
                    uint32_t brow = buf + b_rowoff;
#pragma unroll
                    for (int p = 0; p < 4; p++) ldsm4t(&Bf[0][4 * p], brow + b_pu[p]);
                }
#pragma unroll
                for (int h = 0; h < 2; h++) {
                    const int cur = h & 1, nxt = cur ^ 1;
                    if (h < 1) {
                        uint32_t aoff = (((uint32_t)((kb * 2 + 1) << 1) ^ a_cbs) << 4);
                        ldsm4(&Af[nxt][0], a_lrow0 + aoff);
                        ldsm4(&Af[nxt][4], a_lrow1 + aoff);
                        uint32_t brow = buf + b_rowoff + 16384u;
#pragma unroll
                        for (int p = 0; p < 4; p++) ldsm4t(&Bf[nxt][4 * p], brow + b_pu[p]);
                    }
#pragma unroll
                    for (int p = 0; p < 4; p++) {
                        mma_bf16(acc[0][2 * p + 0], &Af[cur][0], Bf[cur][4 * p + 0], Bf[cur][4 * p + 1]);
                        mma_bf16(acc[0][2 * p + 1], &Af[cur][0], Bf[cur][4 * p + 2], Bf[cur][4 * p + 3]);
                        mma_bf16(acc[1][2 * p + 0], &Af[cur][4], Bf[cur][4 * p + 0], Bf[cur][4 * p + 1]);
                        mma_bf16(acc[1][2 * p + 1], &Af[cur][4], Bf[cur][4 * p + 2], Bf[cur][4 * p + 3]);
                    }
                }
            }
            asm volatile("cp.async.wait_group 0;" ::: "memory");
            __syncthreads();
            if (kb == 0 && tid < 16) flagsm[((it + 1) & 1) * 16 + tid] = 0u;
        }

        if (it < 8) {
            bool nzlo = false, nzhi = false;
            const int wslot = (it + 1) & 1;
#pragma unroll
            for (int fm = 0; fm < 2; fm++)
#pragma unroll
            for (int rh = 0; rh < 2; rh++) {
                int rl = fm * 16 + rh * 8 + r4;
                const float* urow = u + (size_t)(grow0 + rl) * DIMN;
                uint32_t abase = sb + A_OFF + (uint32_t)rl * 1024u + (uint32_t)(c2 * 2);
                uint32_t sw = (uint32_t)(rl & 7);
#pragma unroll
                for (int ni = 0; ni < 8; ni++) {
                    float v0 = acc[fm][ni][rh * 2 + 0];
                    float v1 = acc[fm][ni][rh * 2 + 1];
                    float s0 = fabsf(v0) - lam, s1 = fabsf(v1) - lam;
                    float a0 = (s0 > 0.0f) ? copysignf(s0, v0) : 0.0f;
                    float a1 = (s1 > 0.0f) ? copysignf(s1, v1) : 0.0f;
                    bool nz = (a0 != 0.0f) || (a1 != 0.0f);
                    if (ni < 4) nzlo |= nz; else nzhi |= nz;
                    __nv_bfloat162 h2 = __floats2bfloat162_rn(a0, a1);
                    uint32_t aaddr = abase + (((un0 + (uint32_t)ni) ^ sw) << 4);
                    asm volatile("st.shared.b32 [%0], %1;" :: "r"(aaddr), "r"(*(uint32_t*)&h2) : "memory");
                    float2 uv = *(const float2*)(urow + n0 + ni * 8 + c2);
                    acc[fm][ni][rh * 2 + 0] = fmaf(OMETA, v0, ETA * uv.x);
                    acc[fm][ni][rh * 2 + 1] = fmaf(OMETA, v1, ETA * uv.y);
                }
            }
            bool wlo = __any_sync(0xFFFFFFFFu, nzlo);
            bool whi = __any_sync(0xFFFFFFFFu, nzhi);
            if (lane == 0) {
                if (wlo) atomicOr(&flagsm[wslot * 16 + 2 * wn + 0], 1u);
                if (whi) atomicOr(&flagsm[wslot * 16 + 2 * wn + 1], 1u);
            }
            __syncthreads();
        } else {
            // final: a10 = soft(v10) -> out
#pragma unroll
            for (int fm = 0; fm < 2; fm++)
#pragma unroll
            for (int rh = 0; rh < 2; rh++) {
                int rl = fm * 16 + rh * 8 + r4;
                float* orow = out + (size_t)(grow0 + rl) * DIMN;
#pragma unroll
                for (int ni = 0; ni < 8; ni++) {
                    float v0 = acc[fm][ni][rh * 2 + 0];
                    float v1 = acc[fm][ni][rh * 2 + 1];
                    float s0 = fabsf(v0) - lam, s1 = fabsf(v1) - lam;
                    float2 o;
                    o.x = (s0 > 0.0f) ? copysignf(s0, v0) : 0.0f;
                    o.y = (s1 > 0.0f) ? copysignf(s1, v1) : 0.0f;
                    *(float2*)(orow + n0 + ni * 8 + c2) = o;
                }
            }
        }
    }
}

extern "C" void kernel_launch(void* const* d_in, const int* in_sizes, int n_in,
                              void* d_out, int out_size) {
    const float* u = nullptr;
    const float* G = nullptr;
    const float* ll = nullptr;
    for (int i = 0; i < n_in; i++) {
        if (in_sizes[i] == NROWS * DIMN)      u  = (const float*)d_in[i];
        else if (in_sizes[i] == DIMN * DIMN)  G  = (const float*)d_in[i];
        else                                  ll = (const float*)d_in[i];
    }
    float* out = (float*)d_out;

    lca_prep_kernel<<<DIMN, DIMN>>>(G);

    cudaFuncSetAttribute(lca_main_kernel,
                         cudaFuncAttributeMaxDynamicSharedMemorySize, SMEM_TOTAL);
    lca_main_kernel<<<NCTAS, NTHREADS, SMEM_TOTAL>>>(u, ll, out);
}

// round 6
// speedup vs baseline: 1.0053x; 1.0053x over previous
#include <cuda_runtime.h>
#include <cuda_bf16.h>
#include <cstdint>

#define DIMN 512
#define MT   64
#define NROWS 65536
#define NCTAS (NROWS / MT)        // 1024
#define NTHREADS 512
#define ETA   0.1f
#define OMETA 0.9f
#define SC    512.0f              // acc domain = SC * v
#define ISC   (1.0f/512.0f)

// smem: a-tile [64 rows][1024B] fp8 (cu 0..31 used) = 64KB + 4 G buffers 32KB + flags
static constexpr uint32_t A_OFF  = 0;
static constexpr uint32_t GB_OFF = 65536;         // + b*32768, b=0..3
static constexpr uint32_t FL_OFF = 196608;        // flags[2][8]
static constexpr uint32_t SMEM_TOTAL = 196672;

#define NCH_TOTAL (9 * 8)         // 72 chunks of 32 kp-rows (k64 each)

// G'' = 512 * (-eta*0.5*(G+G^T), diag 0) as e4m3 pairs: [kp][n] b16 units = {k=2kp, k=2kp+1}
__device__ unsigned short g_gp8[256 * DIMN];

__global__ void lca_prep_kernel(const float* __restrict__ G) {
    int idx = blockIdx.x * blockDim.x + threadIdx.x;   // 131072
    int kp = idx >> 9, n = idx & 511;
    int k0 = 2 * kp, k1 = 2 * kp + 1;
    // -eta*0.5*512 = -25.6
    float w0 = (k0 == n) ? 0.0f : -25.6f * (G[k0 * DIMN + n] + G[n * DIMN + k0]);
    float w1 = (k1 == n) ? 0.0f : -25.6f * (G[k1 * DIMN + n] + G[n * DIMN + k1]);
    unsigned short h;
    asm("cvt.rn.satfinite.e4m3x2.f32 %0, %1, %2;" : "=h"(h) : "f"(w1), "f"(w0));
    g_gp8[idx] = h;
}

__device__ __forceinline__ uint32_t smem_u32(const void* p) {
    uint32_t a;
    asm("{ .reg .u64 t; cvta.to.shared.u64 t, %1; cvt.u32.u64 %0, t; }" : "=r"(a) : "l"(p));
    return a;
}
__device__ __forceinline__ void ldsm4(uint32_t* r, uint32_t addr) {
    asm volatile("ldmatrix.sync.aligned.m8n8.x4.shared.b16 {%0,%1,%2,%3}, [%4];"
                 : "=r"(r[0]), "=r"(r[1]), "=r"(r[2]), "=r"(r[3]) : "r"(addr));
}
__device__ __forceinline__ void ldsm4t(uint32_t* r, uint32_t addr) {
    asm volatile("ldmatrix.sync.aligned.m8n8.x4.trans.shared.b16 {%0,%1,%2,%3}, [%4];"
                 : "=r"(r[0]), "=r"(r[1]), "=r"(r[2]), "=r"(r[3]) : "r"(addr));
}
__device__ __forceinline__ void mma_fp8(float* c, const uint32_t* a, uint32_t b0, uint32_t b1) {
    asm volatile("mma.sync.aligned.m16n8k32.row.col.f32.e4m3.e4m3.f32 "
                 "{%0,%1,%2,%3}, {%4,%5,%6,%7}, {%8,%9}, {%0,%1,%2,%3};"
                 : "+f"(c[0]), "+f"(c[1]), "+f"(c[2]), "+f"(c[3])
                 : "r"(a[0]), "r"(a[1]), "r"(a[2]), "r"(a[3]), "r"(b0), "r"(b1));
}
__device__ __forceinline__ void cp_async16(uint32_t dst, const void* src) {
    asm volatile("cp.async.cg.shared.global [%0], [%1], 16;" :: "r"(dst), "l"(src) : "memory");
}
__device__ __forceinline__ unsigned short fp8pair(float hi, float lo) {
    unsigned short h;
    asm("cvt.rn.satfinite.e4m3x2.f32 %0, %1, %2;" : "=h"(h) : "f"(hi), "f"(lo));
    return h;
}

// load G chunk rb (32 kp-rows, 32KB) into buffer boff; 2048 units / 512 thr = 4 each
__device__ __forceinline__ void load_chunk32(uint32_t sb, uint32_t boff, int rb, int tid) {
    const char* src = (const char*)g_gp8 + (size_t)rb * 32768 + (size_t)tid * 16;
#pragma unroll
    for (int j = 0; j < 4; j++) {
        int q = tid + j * 512;
        int r = q >> 6, cu = q & 63;
        uint32_t dst = sb + boff + (uint32_t)r * 1024u + ((uint32_t)(cu ^ (r & 7)) << 4);
        cp_async16(dst, src + j * 8192);
    }
    asm volatile("cp.async.commit_group;" ::: "memory");
}

__global__ __launch_bounds__(NTHREADS, 1)
void lca_main_kernel(const float* __restrict__ u,
                     const float* __restrict__ log_lam,
                     float* __restrict__ out) {
    extern __shared__ char smem[];
    const uint32_t sb = smem_u32(smem);
    uint32_t* flagsm = reinterpret_cast<uint32_t*>(smem + FL_OFF);   // [2][8]
    const int tid  = threadIdx.x;
    const int lane = tid & 31;
    const int warp = tid >> 5;
    const int wm = warp >> 3;              // 0..1
    const int wn = warp & 7;               // 0..7
    const int m0 = wm * 32;
    const int n0 = wn * 64;
    const uint32_t un0 = (uint32_t)(n0 >> 3);
    const int grow0 = blockIdx.x * MT;
    const float lam  = expf(log_lam[0]);
    const float SLAM = SC * lam;
    const int r4 = lane >> 2;
    const int c2 = (lane & 3) * 2;

    float acc[2][8][4];                    // scaled domain: acc = SC * v

    const uint32_t a_lrow0 = sb + A_OFF + (uint32_t)(m0 + (lane & 15)) * 1024u;
    const uint32_t a_lrow1 = a_lrow0 + 16u * 1024u;
    const uint32_t a_cbs = ((uint32_t)(lane >> 4)) ^ ((uint32_t)(lane & 7));
    const uint32_t b_rowoff = (uint32_t)(lane & 15) * 1024u;
    uint32_t b_pu[4];
#pragma unroll
    for (int p = 0; p < 4; p++)
        b_pu[p] = (((un0 + (uint32_t)(2 * p) + (uint32_t)(lane >> 4)) ^ (uint32_t)(lane & 7)) << 4);

    // epilogue a-store addressing: ucol = wn*32 + c2/2 + ni*4 (b16 unit col)
    const uint32_t ucb = (uint32_t)(wn * 32 + (c2 >> 1));

    if (tid < 16) flagsm[tid] = 0u;
    load_chunk32(sb, GB_OFF + 0 * 32768u, 0, tid);
    load_chunk32(sb, GB_OFF + 1 * 32768u, 1, tid);
    load_chunk32(sb, GB_OFF + 2 * 32768u, 2, tid);
    __syncthreads();   // flags cleared before any atomicOr

    // ---- init: v1 = eta*u ; a1 = soft(v1,lam) -> fp8 SMEM + flags ; acc = SC*(0.9*v1 + 0.1*u) ----
    {
        bool nzw = false;
#pragma unroll
        for (int fm = 0; fm < 2; fm++)
#pragma unroll
        for (int rh = 0; rh < 2; rh++) {
            int rl = m0 + fm * 16 + rh * 8 + r4;
            const float* urow = u + (size_t)(grow0 + rl) * DIMN;
            uint32_t arow = sb + A_OFF + (uint32_t)rl * 1024u;
            uint32_t sw = (uint32_t)(rl & 7);
#pragma unroll
            for (int ni = 0; ni < 8; ni++) {
                float2 uv = *(const float2*)(urow + n0 + ni * 8 + c2);
                float v0 = ETA * uv.x, v1 = ETA * uv.y;
                float s0 = fabsf(v0) - lam, s1 = fabsf(v1) - lam;
                float a0 = (s0 > 0.0f) ? copysignf(s0, v0) : 0.0f;
                float a1 = (s1 > 0.0f) ? copysignf(s1, v1) : 0.0f;
                nzw |= (a0 != 0.0f) || (a1 != 0.0f);
                unsigned short hp = fp8pair(a1, a0);
                uint32_t ucol = ucb + (uint32_t)(ni * 4);
                uint32_t aaddr = arow + (((ucol >> 3) ^ sw) << 4) + (ucol & 7) * 2;
                asm volatile("st.shared.u16 [%0], %1;" :: "r"(aaddr), "h"(hp) : "memory");
                acc[fm][ni][rh * 2 + 0] = SC * fmaf(OMETA, v0, ETA * uv.x);
                acc[fm][ni][rh * 2 + 1] = SC * fmaf(OMETA, v1, ETA * uv.y);
            }
        }
        if (__any_sync(0xFFFFFFFFu, nzw) && lane == 0) atomicOr(&flagsm[wn], 1u);
    }

    // ---- 9 iterations, 8 chunks (32 kp-rows = k64) each, distance-3 prefetch ----
#pragma unroll 1
    for (int it = 0; it < 9; it++) {
        const int slot = it & 1;
#pragma unroll 1
        for (int kb = 0; kb < 8; kb++) {
            const int c = it * 8 + kb;
            if (c < 70)      { asm volatile("cp.async.wait_group 2;" ::: "memory"); }
            else if (c == 70){ asm volatile("cp.async.wait_group 1;" ::: "memory"); }
            else             { asm volatile("cp.async.wait_group 0;" ::: "memory"); }
            __syncthreads();   // chunk c visible to all; buffer (c+3)&3 free
            if (kb == 0 && tid < 8) flagsm[((it + 1) & 1) * 8 + tid] = 0u;
            if (c + 3 < NCH_TOTAL)
                load_chunk32(sb, GB_OFF + (uint32_t)((c + 3) & 3) * 32768u, (kb + 3) & 7, tid);

            if (flagsm[slot * 8 + kb]) {
                const uint32_t buf = sb + GB_OFF + (uint32_t)(c & 3) * 32768u;
                uint32_t Af[2][8], Bf[2][16];
                {   // preload k32 step 0 (cu = kb*4)
                    uint32_t aoff = (((uint32_t)(kb << 2) ^ a_cbs) << 4);
                    ldsm4(&Af[0][0], a_lrow0 + aoff);
                    ldsm4(&Af[0][4], a_lrow1 + aoff);
                    uint32_t brow = buf + b_rowoff;
#pragma unroll
                    for (int p = 0; p < 4; p++) ldsm4t(&Bf[0][4 * p], brow + b_pu[p]);
                }
#pragma unroll
                for (int h = 0; h < 2; h++) {
                    const int cur = h & 1, nxt = cur ^ 1;
                    if (h < 1) {   // preload step 1 (cu = kb*4+2)
                        uint32_t aoff = ((((uint32_t)(kb << 2) | 2u) ^ a_cbs) << 4);
                        ldsm4(&Af[nxt][0], a_lrow0 + aoff);
                        ldsm4(&Af[nxt][4], a_lrow1 + aoff);
                        uint32_t brow = buf + b_rowoff + 16384u;
#pragma unroll
                        for (int p = 0; p < 4; p++) ldsm4t(&Bf[nxt][4 * p], brow + b_pu[p]);
                    }
#pragma unroll
                    for (int p = 0; p < 4; p++) {
                        mma_fp8(acc[0][2 * p + 0], &Af[cur][0], Bf[cur][4 * p + 0], Bf[cur][4 * p + 1]);
                        mma_fp8(acc[0][2 * p + 1], &Af[cur][0], Bf[cur][4 * p + 2], Bf[cur][4 * p + 3]);
                        mma_fp8(acc[1][2 * p + 0], &Af[cur][4], Bf[cur][4 * p + 0], Bf[cur][4 * p + 1]);
                        mma_fp8(acc[1][2 * p + 1], &Af[cur][4], Bf[cur][4 * p + 2], Bf[cur][4 * p + 3]);
                    }
                }
            }
        }
        __syncthreads();   // all MMAs of this iteration done before A-tile rewrite

        if (it < 8) {
            bool nzw = false;
            const int wslot = (it + 1) & 1;
#pragma unroll
            for (int fm = 0; fm < 2; fm++)
#pragma unroll
            for (int rh = 0; rh < 2; rh++) {
                int rl = m0 + fm * 16 + rh * 8 + r4;
                const float* urow = u + (size_t)(grow0 + rl) * DIMN;
                uint32_t arow = sb + A_OFF + (uint32_t)rl * 1024u;
                uint32_t sw = (uint32_t)(rl & 7);
#pragma unroll
                for (int ni = 0; ni < 8; ni++) {
                    float w0 = acc[fm][ni][rh * 2 + 0];   // = SC * v
                    float w1 = acc[fm][ni][rh * 2 + 1];
                    float s0 = fabsf(w0) - SLAM, s1 = fabsf(w1) - SLAM;
                    float a0 = (s0 > 0.0f) ? copysignf(s0 * ISC, w0) : 0.0f;  // true-scale a
                    float a1 = (s1 > 0.0f) ? copysignf(s1 * ISC, w1) : 0.0f;
                    nzw |= (a0 != 0.0f) || (a1 != 0.0f);
                    unsigned short hp = fp8pair(a1, a0);
                    uint32_t ucol = ucb + (uint32_t)(ni * 4);
                    uint32_t aaddr = arow + (((ucol >> 3) ^ sw) << 4) + (ucol & 7) * 2;
                    asm volatile("st.shared.u16 [%0], %1;" :: "r"(aaddr), "h"(hp) : "memory");
                    float2 uv = *(const float2*)(urow + n0 + ni * 8 + c2);
                    acc[fm][ni][rh * 2 + 0] = fmaf(OMETA, w0, (SC * ETA) * uv.x);
                    acc[fm][ni][rh * 2 + 1] = fmaf(OMETA, w1, (SC * ETA) * uv.y);
                }
            }
            if (__any_sync(0xFFFFFFFFu, nzw) && lane == 0)
                atomicOr(&flagsm[wslot * 8 + wn], 1u);
        } else {
            // final: a10 = soft(v10) -> out (true scale)
#pragma unroll
            for (int fm = 0; fm < 2; fm++)
#pragma unroll
            for (int rh = 0; rh < 2; rh++) {
                int rl = m0 + fm * 16 + rh * 8 + r4;
                float* orow = out + (size_t)(grow0 + rl) * DIMN;
#pragma unroll
                for (int ni = 0; ni < 8; ni++) {
                    float w0 = acc[fm][ni][rh * 2 + 0];
                    float w1 = acc[fm][ni][rh * 2 + 1];
                    float s0 = fabsf(w0) - SLAM, s1 = fabsf(w1) - SLAM;
                    float2 o;
                    o.x = (s0 > 0.0f) ? copysignf(s0 * ISC, w0) : 0.0f;
                    o.y = (s1 > 0.0f) ? copysignf(s1 * ISC, w1) : 0.0f;
                    *(float2*)(orow + n0 + ni * 8 + c2) = o;
                }
            }
        }
    }
}

extern "C" void kernel_launch(void* const* d_in, const int* in_sizes, int n_in,
                              void* d_out, int out_size) {
    const float* u = nullptr;
    const float* G = nullptr;
    const float* ll = nullptr;
    for (int i = 0; i < n_in; i++) {
        if (in_sizes[i] == NROWS * DIMN)      u  = (const float*)d_in[i];
        else if (in_sizes[i] == DIMN * DIMN)  G  = (const float*)d_in[i];
        else                                  ll = (const float*)d_in[i];
    }
    float* out = (float*)d_out;

    lca_prep_kernel<<<256, 512>>>(G);

    cudaFuncSetAttribute(lca_main_kernel,
                         cudaFuncAttributeMaxDynamicSharedMemorySize, SMEM_TOTAL);
    lca_main_kernel<<<NCTAS, NTHREADS, SMEM_TOTAL>>>(u, ll, out);
}